// round 1
// baseline (speedup 1.0000x reference)
#include <cuda_runtime.h>
#include <cuda_bf16.h>

// ---------------- scratch (allocation-free: __device__ globals) ----------------
__device__ float g_a1[64*32*63*63];     // enc1 out
__device__ float g_a2[64*64*32*32];     // enc2 out
__device__ float g_z [64*64*32*32];     // enc3 out (z)
__device__ float g_e [64*64*32*32];     // quantized (q in NCHW)
__device__ float g_d1[64*64*64*64];     // dec1 out
__device__ float g_d2[64*32*128*128];   // dec2 out
__device__ double g_vq_loss;
__device__ double g_recon;

__global__ void k_zero() { g_vq_loss = 0.0; g_recon = 0.0; }

// ---------------- enc conv1: 3->32, k3 s2 p1, 125->63, relu ----------------
__global__ void k_conv1(const float* __restrict__ x, const float* __restrict__ w,
                        const float* __restrict__ b) {
    int idx = blockIdx.x * 256 + threadIdx.x;
    if (idx >= 64*32*63*63) return;
    int ow = idx % 63; int t = idx / 63;
    int oh = t % 63;  t /= 63;
    int co = t % 32;  int n = t / 32;
    float acc = b[co];
    const float* xb = x + n*3*125*125;
    const float* wb = w + co*3*9;
    #pragma unroll
    for (int ci = 0; ci < 3; ci++) {
        #pragma unroll
        for (int kh = 0; kh < 3; kh++) {
            int ih = 2*oh + kh - 1;
            if ((unsigned)ih < 125u) {
                #pragma unroll
                for (int kw = 0; kw < 3; kw++) {
                    int iw = 2*ow + kw - 1;
                    if ((unsigned)iw < 125u)
                        acc += wb[ci*9 + kh*3 + kw] * xb[(ci*125 + ih)*125 + iw];
                }
            }
        }
    }
    g_a1[idx] = fmaxf(acc, 0.f);
}

// ---------------- enc conv2: 32->64, k3 s2 p1, 63->32, relu (CO_BLK=8) ------
__global__ void k_conv2(const float* __restrict__ w, const float* __restrict__ b) {
    int idx = blockIdx.x * 256 + threadIdx.x;       // 524288 total
    int ow  = idx & 31; int t = idx >> 5;
    int oh  = t & 31;   t >>= 5;
    int cog = t & 7;    int n = t >> 3;
    int co0 = cog * 8;
    float acc[8];
    #pragma unroll
    for (int j = 0; j < 8; j++) acc[j] = b[co0 + j];
    const float* ib = g_a1 + n*32*63*63;
    for (int ci = 0; ci < 32; ci++) {
        float in[9];
        #pragma unroll
        for (int kh = 0; kh < 3; kh++) {
            int ih = 2*oh + kh - 1;
            #pragma unroll
            for (int kw = 0; kw < 3; kw++) {
                int iw = 2*ow + kw - 1;
                in[kh*3+kw] = ((unsigned)ih < 63u && (unsigned)iw < 63u)
                              ? ib[(ci*63 + ih)*63 + iw] : 0.f;
            }
        }
        #pragma unroll
        for (int j = 0; j < 8; j++) {
            const float* wb = w + ((co0 + j)*32 + ci)*9;
            #pragma unroll
            for (int tt = 0; tt < 9; tt++) acc[j] += wb[tt] * in[tt];
        }
    }
    int ohw = oh*32 + ow;
    #pragma unroll
    for (int j = 0; j < 8; j++)
        g_a2[(n*64 + co0 + j)*1024 + ohw] = fmaxf(acc[j], 0.f);
}

// ---------------- enc conv3: 64->64 1x1 (CO_BLK=16, weights in smem) --------
__global__ void k_conv3(const float* __restrict__ w, const float* __restrict__ b) {
    __shared__ float ws[16*64];
    int bid  = blockIdx.x;                 // 1024 = 64n * 4cog * 4tile
    int tile = bid & 3;
    int cog  = (bid >> 2) & 3;
    int n    = bid >> 4;
    int co0  = cog * 16;
    for (int i = threadIdx.x; i < 1024; i += 256) ws[i] = w[co0*64 + i];
    __syncthreads();
    int hw = tile*256 + threadIdx.x;
    float acc[16];
    #pragma unroll
    for (int j = 0; j < 16; j++) acc[j] = b[co0 + j];
    const float* ib = g_a2 + n*64*1024;
    for (int ci = 0; ci < 64; ci++) {
        float v = ib[ci*1024 + hw];
        #pragma unroll
        for (int j = 0; j < 16; j++) acc[j] += ws[j*64 + ci] * v;
    }
    #pragma unroll
    for (int j = 0; j < 16; j++) g_z[(n*64 + co0 + j)*1024 + hw] = acc[j];
}

// ---------------- VQ: argmin over 512 codes + gather + e-store + loss -------
__global__ void k_vq(const float* __restrict__ codebook) {
    __shared__ float4 cbs[128][16];   // 32KB chunk of codebook
    __shared__ float  cns[128];
    __shared__ float  wsum[8];
    int n  = blockIdx.x * 256 + threadIdx.x;    // exact: 256 blocks
    int bb = n >> 10;
    int hw = n & 1023;
    const float* zb = g_z + bb*65536 + hw;
    float zv[64];
    #pragma unroll
    for (int d = 0; d < 64; d++) zv[d] = zb[d*1024];
    float best = 3.0e38f; int bidx = 0;
    for (int c = 0; c < 4; c++) {
        __syncthreads();
        const float4* src = (const float4*)(codebook + c*128*64);
        for (int i = threadIdx.x; i < 2048; i += 256)
            ((float4*)cbs)[i] = src[i];
        __syncthreads();
        if (threadIdx.x < 128) {
            const float* cc = (const float*)cbs[threadIdx.x];
            float s = 0.f;
            #pragma unroll
            for (int d = 0; d < 64; d++) s += cc[d]*cc[d];
            cns[threadIdx.x] = s;
        }
        __syncthreads();
        for (int k = 0; k < 128; k++) {
            float dot = 0.f;
            #pragma unroll
            for (int q = 0; q < 16; q++) {
                float4 cv = cbs[k][q];
                dot += cv.x*zv[4*q]   + cv.y*zv[4*q+1]
                     + cv.z*zv[4*q+2] + cv.w*zv[4*q+3];
            }
            float dist = cns[k] - 2.f*dot;
            if (dist < best) { best = dist; bidx = c*128 + k; }
        }
    }
    // gather chosen code, write e (NCHW), accumulate (q - z)^2
    const float* cbest = codebook + bidx*64;
    float* eb = g_e + bb*65536 + hw;
    float ls = 0.f;
    #pragma unroll
    for (int d = 0; d < 64; d++) {
        float qv = cbest[d];
        float df = qv - zv[d];
        ls += df*df;
        eb[d*1024] = qv;
    }
    #pragma unroll
    for (int off = 16; off; off >>= 1) ls += __shfl_down_sync(0xffffffffu, ls, off);
    if ((threadIdx.x & 31) == 0) wsum[threadIdx.x >> 5] = ls;
    __syncthreads();
    if (threadIdx.x == 0) {
        float s = 0.f;
        #pragma unroll
        for (int i = 0; i < 8; i++) s += wsum[i];
        atomicAdd(&g_vq_loss, (double)s);
    }
}

// ---------------- decT1: 64->64, k3 s2 p1 op1, 32->64, relu -----------------
// parity decomposition: thread owns output quad (2m,2l..2m+1,2l+1), CO_BLK=8
__global__ void k_dec1(const float* __restrict__ w, const float* __restrict__ b) {
    __shared__ float ws[64][8][9];     // 18KB: w[ci][co0+j][kh*3+kw]
    int bid  = blockIdx.x;             // 2048 = 64n * 8cog * 4quad
    int quad = bid & 3;
    int cog  = (bid >> 2) & 7;
    int n    = bid >> 5;
    int co0  = cog * 8;
    for (int i = threadIdx.x; i < 64*8*9; i += 256) {
        int t  = i % 9;
        int j  = (i/9) % 8;
        int ci = i / 72;
        ws[ci][j][t] = w[(ci*64 + co0 + j)*9 + t];
    }
    __syncthreads();
    int l = (quad & 1)*16 + (threadIdx.x & 15);
    int m = (quad >> 1)*16 + (threadIdx.x >> 4);
    float acc[8][4];
    #pragma unroll
    for (int j = 0; j < 8; j++) {
        float bv = b[co0 + j];
        acc[j][0]=bv; acc[j][1]=bv; acc[j][2]=bv; acc[j][3]=bv;
    }
    const float* ib = g_e + n*64*1024;
    bool mok = (m+1) < 32, lok = (l+1) < 32;
    for (int ci = 0; ci < 64; ci++) {
        const float* p = ib + ci*1024 + m*32 + l;
        float i00 = p[0];
        float i01 = lok ? p[1]  : 0.f;
        float i10 = mok ? p[32] : 0.f;
        float i11 = (mok && lok) ? p[33] : 0.f;
        #pragma unroll
        for (int j = 0; j < 8; j++) {
            const float* W = ws[ci][j];
            acc[j][0] += W[4]*i00;
            acc[j][1] += W[3]*i01 + W[5]*i00;
            acc[j][2] += W[1]*i10 + W[7]*i00;
            acc[j][3] += W[0]*i11 + W[2]*i10 + W[6]*i01 + W[8]*i00;
        }
    }
    float* ob = g_d1 + (n*64 + co0)*4096;
    #pragma unroll
    for (int j = 0; j < 8; j++) {
        float* o = ob + j*4096 + (2*m)*64 + 2*l;
        o[0]  = fmaxf(acc[j][0], 0.f);
        o[1]  = fmaxf(acc[j][1], 0.f);
        o[64] = fmaxf(acc[j][2], 0.f);
        o[65] = fmaxf(acc[j][3], 0.f);
    }
}

// ---------------- decT2: 64->32, k3 s2 p1 op1, 64->128, relu ----------------
__global__ void k_dec2(const float* __restrict__ w, const float* __restrict__ b) {
    __shared__ float ws[64][8][9];
    int bid  = blockIdx.x;             // 4096 = 64n * 4cog * 16tile
    int tile = bid & 15;
    int cog  = (bid >> 4) & 3;
    int n    = bid >> 6;
    int co0  = cog * 8;
    for (int i = threadIdx.x; i < 64*8*9; i += 256) {
        int t  = i % 9;
        int j  = (i/9) % 8;
        int ci = i / 72;
        ws[ci][j][t] = w[(ci*32 + co0 + j)*9 + t];
    }
    __syncthreads();
    int l = (tile & 3)*16 + (threadIdx.x & 15);
    int m = (tile >> 2)*16 + (threadIdx.x >> 4);
    float acc[8][4];
    #pragma unroll
    for (int j = 0; j < 8; j++) {
        float bv = b[co0 + j];
        acc[j][0]=bv; acc[j][1]=bv; acc[j][2]=bv; acc[j][3]=bv;
    }
    const float* ib = g_d1 + n*64*4096;
    bool mok = (m+1) < 64, lok = (l+1) < 64;
    for (int ci = 0; ci < 64; ci++) {
        const float* p = ib + ci*4096 + m*64 + l;
        float i00 = p[0];
        float i01 = lok ? p[1]  : 0.f;
        float i10 = mok ? p[64] : 0.f;
        float i11 = (mok && lok) ? p[65] : 0.f;
        #pragma unroll
        for (int j = 0; j < 8; j++) {
            const float* W = ws[ci][j];
            acc[j][0] += W[4]*i00;
            acc[j][1] += W[3]*i01 + W[5]*i00;
            acc[j][2] += W[1]*i10 + W[7]*i00;
            acc[j][3] += W[0]*i11 + W[2]*i10 + W[6]*i01 + W[8]*i00;
        }
    }
    float* ob = g_d2 + (n*32 + co0)*16384;
    #pragma unroll
    for (int j = 0; j < 8; j++) {
        float* o = ob + j*16384 + (2*m)*128 + 2*l;
        o[0]   = fmaxf(acc[j][0], 0.f);
        o[1]   = fmaxf(acc[j][1], 0.f);
        o[128] = fmaxf(acc[j][2], 0.f);
        o[129] = fmaxf(acc[j][3], 0.f);
    }
}

// ---------------- decT3: 32->3, k2 s1 p2, 128->125 + recon loss -------------
// gather conv: y[oh,ow] = sum_{kh,kw in {0,1}} w[ci][co][kh][kw]*in[oh+2-kh][ow+2-kw]
// all taps always in-bounds (ih in [1,126], iw in [1,126]).
__global__ void k_dec3(const float* __restrict__ w, const float* __restrict__ bs,
                       const float* __restrict__ x, float* __restrict__ out) {
    __shared__ float ws[384];          // w[ci][co][kh][kw] linear
    __shared__ float wsum[8];
    for (int i = threadIdx.x; i < 384; i += 256) ws[i] = w[i];
    __syncthreads();
    int idx = blockIdx.x * 256 + threadIdx.x;
    float lsum = 0.f;
    if (idx < 1000000) {
        int ow = idx % 125; int t = idx / 125;
        int oh = t % 125;   int n = t / 125;
        float acc[3] = { bs[0], bs[1], bs[2] };
        const float* ib = g_d2 + n*32*16384;
        const float* p  = ib + (oh+1)*128 + (ow+1);
        for (int ci = 0; ci < 32; ci++) {
            const float* q = p + ci*16384;
            float i11 = q[0];    // kh=1,kw=1
            float i12 = q[1];    // kh=1,kw=0
            float i21 = q[128];  // kh=0,kw=1
            float i22 = q[129];  // kh=0,kw=0
            #pragma unroll
            for (int co = 0; co < 3; co++) {
                const float* W = ws + ci*12 + co*4;
                acc[co] += W[0]*i22 + W[1]*i21 + W[2]*i12 + W[3]*i11;
            }
        }
        #pragma unroll
        for (int co = 0; co < 3; co++) {
            int oi = ((n*3 + co)*125 + oh)*125 + ow;
            out[oi] = acc[co];
            float d = acc[co] - x[oi];
            lsum += d*d;
        }
    }
    #pragma unroll
    for (int off = 16; off; off >>= 1) lsum += __shfl_down_sync(0xffffffffu, lsum, off);
    if ((threadIdx.x & 31) == 0) wsum[threadIdx.x >> 5] = lsum;
    __syncthreads();
    if (threadIdx.x == 0) {
        float s = 0.f;
        #pragma unroll
        for (int i = 0; i < 8; i++) s += wsum[i];
        atomicAdd(&g_recon, (double)s);
    }
}

// ---------------- finalize: scalars ----------------
__global__ void k_final(float* __restrict__ out) {
    double mse = g_vq_loss / (65536.0 * 64.0);
    float eq  = (float)(1.25 * mse);          // q_latent + 0.25*e_latent (identical fwd)
    float rec = (float)g_recon;
    out[0] = eq + rec;
    out[1] = eq;
    out[2] = rec;
}

extern "C" void kernel_launch(void* const* d_in, const int* in_sizes, int n_in,
                              void* d_out, int out_size) {
    const float* x   = (const float*)d_in[0];
    const float* ew1 = (const float*)d_in[1];
    const float* eb1 = (const float*)d_in[2];
    const float* ew2 = (const float*)d_in[3];
    const float* eb2 = (const float*)d_in[4];
    const float* ew3 = (const float*)d_in[5];
    const float* eb3 = (const float*)d_in[6];
    const float* cb  = (const float*)d_in[7];
    const float* dw1 = (const float*)d_in[8];
    const float* db1 = (const float*)d_in[9];
    const float* dw2 = (const float*)d_in[10];
    const float* db2 = (const float*)d_in[11];
    const float* dw3 = (const float*)d_in[12];
    const float* db3 = (const float*)d_in[13];
    float* out = (float*)d_out;

    k_zero <<<1, 1>>>();
    k_conv1<<<(64*32*63*63 + 255)/256, 256>>>(x, ew1, eb1);
    k_conv2<<<524288/256, 256>>>(ew2, eb2);
    k_conv3<<<1024, 256>>>(ew3, eb3);
    k_vq   <<<256, 256>>>(cb);
    k_dec1 <<<2048, 256>>>(dw1, db1);
    k_dec2 <<<4096, 256>>>(dw2, db2);
    k_dec3 <<<3907, 256>>>(dw3, db3, x, out + 3);
    k_final<<<1, 1>>>(out);
}

// round 2
// speedup vs baseline: 1.1062x; 1.1062x over previous
#include <cuda_runtime.h>
#include <cuda_bf16.h>

typedef unsigned long long u64;

// ---------------- f32x2 packed-math helpers (sm_103a FFMA2) ----------------
__device__ __forceinline__ u64 pack2(float lo, float hi) {
    u64 r;
    asm("mov.b64 %0, {%1, %2};" : "=l"(r)
        : "r"(__float_as_uint(lo)), "r"(__float_as_uint(hi)));
    return r;
}
__device__ __forceinline__ u64 bcast2(float v) { return pack2(v, v); }
__device__ __forceinline__ void fma2(u64& d, u64 a, u64 b) {
    asm("fma.rn.f32x2 %0, %1, %2, %0;" : "+l"(d) : "l"(a), "l"(b));
}
__device__ __forceinline__ float2 unpack2(u64 v) {
    unsigned lo, hi;
    asm("mov.b64 {%0, %1}, %2;" : "=r"(lo), "=r"(hi) : "l"(v));
    return make_float2(__uint_as_float(lo), __uint_as_float(hi));
}

// ---------------- scratch (allocation-free: __device__ globals) ----------------
__device__ float g_a1[64*32*63*63];     // enc1 out
__device__ float g_a2[64*64*32*32];     // enc2 out
__device__ float g_z [64*64*32*32];     // enc3 out (z)
__device__ float g_e [64*64*32*32];     // quantized (q in NCHW)
__device__ float g_d1[64*64*64*64];     // dec1 out
__device__ float g_d2[64*32*128*128];   // dec2 out
__device__ double g_vq_loss;
__device__ double g_recon;

__global__ void k_zero() { g_vq_loss = 0.0; g_recon = 0.0; }

// ---------------- enc conv1: 3->32, k3 s2 p1, 125->63, relu ----------------
__global__ void k_conv1(const float* __restrict__ x, const float* __restrict__ w,
                        const float* __restrict__ b) {
    int idx = blockIdx.x * 256 + threadIdx.x;
    if (idx >= 64*32*63*63) return;
    int ow = idx % 63; int t = idx / 63;
    int oh = t % 63;  t /= 63;
    int co = t % 32;  int n = t / 32;
    float acc = b[co];
    const float* xb = x + n*3*125*125;
    const float* wb = w + co*3*9;
    #pragma unroll
    for (int ci = 0; ci < 3; ci++) {
        #pragma unroll
        for (int kh = 0; kh < 3; kh++) {
            int ih = 2*oh + kh - 1;
            if ((unsigned)ih < 125u) {
                #pragma unroll
                for (int kw = 0; kw < 3; kw++) {
                    int iw = 2*ow + kw - 1;
                    if ((unsigned)iw < 125u)
                        acc += wb[ci*9 + kh*3 + kw] * xb[(ci*125 + ih)*125 + iw];
                }
            }
        }
    }
    g_a1[idx] = fmaxf(acc, 0.f);
}

// ---------------- enc conv2: 32->64, k3 s2 p1, 63->32, relu ------
// co-paired FFMA2; packed weights in smem
__global__ void k_conv2(const float* __restrict__ w, const float* __restrict__ b) {
    __shared__ float2 wp[32][4][9];     // (w[co0+2jp], w[co0+2jp+1]) per ci,tap
    int bid  = blockIdx.x;              // 2048 = 64n * 8cog * 4tile
    int tile = bid & 3;
    int cog  = (bid >> 2) & 7;
    int n    = bid >> 5;
    int co0  = cog * 8;
    for (int i = threadIdx.x; i < 32*4*9; i += 256) {
        int t  = i % 9;
        int jp = (i/9) & 3;
        int ci = i / 36;
        wp[ci][jp][t] = make_float2(w[((co0 + 2*jp)    *32 + ci)*9 + t],
                                    w[((co0 + 2*jp + 1)*32 + ci)*9 + t]);
    }
    __syncthreads();
    int px = tile*256 + threadIdx.x;
    int ow = px & 31, oh = px >> 5;
    u64 acc[4][1];
    u64 accp[4];
    #pragma unroll
    for (int jp = 0; jp < 4; jp++) accp[jp] = pack2(b[co0+2*jp], b[co0+2*jp+1]);
    (void)acc;
    const float* ib = g_a1 + n*32*63*63;
    for (int ci = 0; ci < 32; ci++) {
        u64 in[9];
        #pragma unroll
        for (int kh = 0; kh < 3; kh++) {
            int ih = 2*oh + kh - 1;
            #pragma unroll
            for (int kw = 0; kw < 3; kw++) {
                int iw = 2*ow + kw - 1;
                float v = ((unsigned)ih < 63u && (unsigned)iw < 63u)
                          ? ib[(ci*63 + ih)*63 + iw] : 0.f;
                in[kh*3+kw] = bcast2(v);
            }
        }
        #pragma unroll
        for (int jp = 0; jp < 4; jp++) {
            const u64* W = (const u64*)wp[ci][jp];
            #pragma unroll
            for (int t = 0; t < 9; t++) fma2(accp[jp], W[t], in[t]);
        }
    }
    int ohw = oh*32 + ow;
    #pragma unroll
    for (int jp = 0; jp < 4; jp++) {
        float2 v = unpack2(accp[jp]);
        g_a2[(n*64 + co0 + 2*jp    )*1024 + ohw] = fmaxf(v.x, 0.f);
        g_a2[(n*64 + co0 + 2*jp + 1)*1024 + ohw] = fmaxf(v.y, 0.f);
    }
}

// ---------------- enc conv3: 64->64 1x1, co-paired FFMA2 --------
__global__ void k_conv3(const float* __restrict__ w, const float* __restrict__ b) {
    __shared__ float2 wsp[64][8];      // (w[co0+2jp][ci], w[co0+2jp+1][ci])
    int bid  = blockIdx.x;             // 1024 = 64n * 4cog * 4tile
    int tile = bid & 3;
    int cog  = (bid >> 2) & 3;
    int n    = bid >> 4;
    int co0  = cog * 16;
    for (int i = threadIdx.x; i < 512; i += 256) {
        int jp = i & 7;
        int ci = i >> 3;
        wsp[ci][jp] = make_float2(w[(co0 + 2*jp)*64 + ci], w[(co0 + 2*jp + 1)*64 + ci]);
    }
    __syncthreads();
    int hw = tile*256 + threadIdx.x;
    u64 accp[8];
    #pragma unroll
    for (int jp = 0; jp < 8; jp++) accp[jp] = pack2(b[co0+2*jp], b[co0+2*jp+1]);
    const float* ib = g_a2 + n*64*1024;
    for (int ci = 0; ci < 64; ci++) {
        u64 vp = bcast2(ib[ci*1024 + hw]);
        const u64* W = (const u64*)wsp[ci];
        #pragma unroll
        for (int jp = 0; jp < 8; jp++) fma2(accp[jp], W[jp], vp);
    }
    #pragma unroll
    for (int jp = 0; jp < 8; jp++) {
        float2 v = unpack2(accp[jp]);
        g_z[(n*64 + co0 + 2*jp    )*1024 + hw] = v.x;
        g_z[(n*64 + co0 + 2*jp + 1)*1024 + hw] = v.y;
    }
}

// ---------------- VQ: argmin over 512 codes (packed dot) + gather + loss -------
__global__ void k_vq(const float* __restrict__ codebook) {
    __shared__ float4 cbs[128][16];   // 32KB chunk of codebook
    __shared__ float  cns[128];
    __shared__ float  wsum[8];
    int n  = blockIdx.x * 256 + threadIdx.x;    // exact: 256 blocks
    int bb = n >> 10;
    int hw = n & 1023;
    const float* zb = g_z + bb*65536 + hw;
    float zv[64];
    #pragma unroll
    for (int d = 0; d < 64; d++) zv[d] = zb[d*1024];
    u64 zp[32];
    #pragma unroll
    for (int q = 0; q < 32; q++) zp[q] = pack2(zv[2*q], zv[2*q+1]);
    float best = 3.0e38f; int bidx = 0;
    for (int c = 0; c < 4; c++) {
        __syncthreads();
        const float4* src = (const float4*)(codebook + c*128*64);
        for (int i = threadIdx.x; i < 2048; i += 256)
            ((float4*)cbs)[i] = src[i];
        __syncthreads();
        if (threadIdx.x < 128) {
            const float* cc = (const float*)cbs[threadIdx.x];
            float s = 0.f;
            #pragma unroll
            for (int d = 0; d < 64; d++) s += cc[d]*cc[d];
            cns[threadIdx.x] = s;
        }
        __syncthreads();
        for (int k = 0; k < 128; k++) {
            const ulonglong2* ck = (const ulonglong2*)cbs[k];
            u64 dotp = 0ull;   // (+0.f, +0.f)
            #pragma unroll
            for (int q2 = 0; q2 < 16; q2++) {
                ulonglong2 cv = ck[q2];
                fma2(dotp, cv.x, zp[2*q2]);
                fma2(dotp, cv.y, zp[2*q2+1]);
            }
            float2 dd = unpack2(dotp);
            float dist = cns[k] - 2.f*(dd.x + dd.y);
            if (dist < best) { best = dist; bidx = c*128 + k; }
        }
    }
    const float* cbest = codebook + bidx*64;
    float* eb = g_e + bb*65536 + hw;
    float ls = 0.f;
    #pragma unroll
    for (int d = 0; d < 64; d++) {
        float qv = cbest[d];
        float df = qv - zv[d];
        ls += df*df;
        eb[d*1024] = qv;
    }
    #pragma unroll
    for (int off = 16; off; off >>= 1) ls += __shfl_down_sync(0xffffffffu, ls, off);
    if ((threadIdx.x & 31) == 0) wsum[threadIdx.x >> 5] = ls;
    __syncthreads();
    if (threadIdx.x == 0) {
        float s = 0.f;
        #pragma unroll
        for (int i = 0; i < 8; i++) s += wsum[i];
        atomicAdd(&g_vq_loss, (double)s);
    }
}

// ---------------- decT1: 64->64, k3 s2 p1 op1, 32->64, relu -----------------
// parity quad per thread, co-paired FFMA2 accumulators
__global__ void k_dec1(const float* __restrict__ w, const float* __restrict__ b) {
    __shared__ float2 wp[64][4][9];    // 18KB: (w[ci][co0+2jp][t], w[ci][co0+2jp+1][t])
    int bid  = blockIdx.x;             // 2048 = 64n * 8cog * 4quad
    int quad = bid & 3;
    int cog  = (bid >> 2) & 7;
    int n    = bid >> 5;
    int co0  = cog * 8;
    for (int i = threadIdx.x; i < 64*4*9; i += 256) {
        int t  = i % 9;
        int jp = (i/9) & 3;
        int ci = i / 36;
        wp[ci][jp][t] = make_float2(w[(ci*64 + co0 + 2*jp    )*9 + t],
                                    w[(ci*64 + co0 + 2*jp + 1)*9 + t]);
    }
    __syncthreads();
    int l = (quad & 1)*16 + (threadIdx.x & 15);
    int m = (quad >> 1)*16 + (threadIdx.x >> 4);
    u64 acc[4][4];
    #pragma unroll
    for (int jp = 0; jp < 4; jp++) {
        u64 bv = pack2(b[co0+2*jp], b[co0+2*jp+1]);
        acc[jp][0]=bv; acc[jp][1]=bv; acc[jp][2]=bv; acc[jp][3]=bv;
    }
    const float* ib = g_e + n*64*1024;
    bool mok = (m+1) < 32, lok = (l+1) < 32;
    for (int ci = 0; ci < 64; ci++) {
        const float* p = ib + ci*1024 + m*32 + l;
        float i00 = p[0];
        float i01 = lok ? p[1]  : 0.f;
        float i10 = mok ? p[32] : 0.f;
        float i11 = (mok && lok) ? p[33] : 0.f;
        u64 P00 = bcast2(i00), P01 = bcast2(i01), P10 = bcast2(i10), P11 = bcast2(i11);
        #pragma unroll
        for (int jp = 0; jp < 4; jp++) {
            const u64* W = (const u64*)wp[ci][jp];
            fma2(acc[jp][0], W[4], P00);
            fma2(acc[jp][1], W[3], P01); fma2(acc[jp][1], W[5], P00);
            fma2(acc[jp][2], W[1], P10); fma2(acc[jp][2], W[7], P00);
            fma2(acc[jp][3], W[0], P11); fma2(acc[jp][3], W[2], P10);
            fma2(acc[jp][3], W[6], P01); fma2(acc[jp][3], W[8], P00);
        }
    }
    float* ob = g_d1 + (n*64 + co0)*4096;
    #pragma unroll
    for (int jp = 0; jp < 4; jp++) {
        float2 a0 = unpack2(acc[jp][0]);
        float2 a1 = unpack2(acc[jp][1]);
        float2 a2 = unpack2(acc[jp][2]);
        float2 a3 = unpack2(acc[jp][3]);
        float* o0 = ob + (2*jp)*4096 + (2*m)*64 + 2*l;
        float* o1 = o0 + 4096;
        *(float2*)(o0)      = make_float2(fmaxf(a0.x,0.f), fmaxf(a1.x,0.f));
        *(float2*)(o0 + 64) = make_float2(fmaxf(a2.x,0.f), fmaxf(a3.x,0.f));
        *(float2*)(o1)      = make_float2(fmaxf(a0.y,0.f), fmaxf(a1.y,0.f));
        *(float2*)(o1 + 64) = make_float2(fmaxf(a2.y,0.f), fmaxf(a3.y,0.f));
    }
}

// ---------------- decT2: 64->32, k3 s2 p1 op1, 64->128, relu ----------------
__global__ void k_dec2(const float* __restrict__ w, const float* __restrict__ b) {
    __shared__ float2 wp[64][4][9];
    int bid  = blockIdx.x;             // 4096 = 64n * 4cog * 16tile
    int tile = bid & 15;
    int cog  = (bid >> 4) & 3;
    int n    = bid >> 6;
    int co0  = cog * 8;
    for (int i = threadIdx.x; i < 64*4*9; i += 256) {
        int t  = i % 9;
        int jp = (i/9) & 3;
        int ci = i / 36;
        wp[ci][jp][t] = make_float2(w[(ci*32 + co0 + 2*jp    )*9 + t],
                                    w[(ci*32 + co0 + 2*jp + 1)*9 + t]);
    }
    __syncthreads();
    int l = (tile & 3)*16 + (threadIdx.x & 15);
    int m = (tile >> 2)*16 + (threadIdx.x >> 4);
    u64 acc[4][4];
    #pragma unroll
    for (int jp = 0; jp < 4; jp++) {
        u64 bv = pack2(b[co0+2*jp], b[co0+2*jp+1]);
        acc[jp][0]=bv; acc[jp][1]=bv; acc[jp][2]=bv; acc[jp][3]=bv;
    }
    const float* ib = g_d1 + n*64*4096;
    bool mok = (m+1) < 64, lok = (l+1) < 64;
    for (int ci = 0; ci < 64; ci++) {
        const float* p = ib + ci*4096 + m*64 + l;
        float i00 = p[0];
        float i01 = lok ? p[1]  : 0.f;
        float i10 = mok ? p[64] : 0.f;
        float i11 = (mok && lok) ? p[65] : 0.f;
        u64 P00 = bcast2(i00), P01 = bcast2(i01), P10 = bcast2(i10), P11 = bcast2(i11);
        #pragma unroll
        for (int jp = 0; jp < 4; jp++) {
            const u64* W = (const u64*)wp[ci][jp];
            fma2(acc[jp][0], W[4], P00);
            fma2(acc[jp][1], W[3], P01); fma2(acc[jp][1], W[5], P00);
            fma2(acc[jp][2], W[1], P10); fma2(acc[jp][2], W[7], P00);
            fma2(acc[jp][3], W[0], P11); fma2(acc[jp][3], W[2], P10);
            fma2(acc[jp][3], W[6], P01); fma2(acc[jp][3], W[8], P00);
        }
    }
    float* ob = g_d2 + (n*32 + co0)*16384;
    #pragma unroll
    for (int jp = 0; jp < 4; jp++) {
        float2 a0 = unpack2(acc[jp][0]);
        float2 a1 = unpack2(acc[jp][1]);
        float2 a2 = unpack2(acc[jp][2]);
        float2 a3 = unpack2(acc[jp][3]);
        float* o0 = ob + (2*jp)*16384 + (2*m)*128 + 2*l;
        float* o1 = o0 + 16384;
        *(float2*)(o0)       = make_float2(fmaxf(a0.x,0.f), fmaxf(a1.x,0.f));
        *(float2*)(o0 + 128) = make_float2(fmaxf(a2.x,0.f), fmaxf(a3.x,0.f));
        *(float2*)(o1)       = make_float2(fmaxf(a0.y,0.f), fmaxf(a1.y,0.f));
        *(float2*)(o1 + 128) = make_float2(fmaxf(a2.y,0.f), fmaxf(a3.y,0.f));
    }
}

// ---------------- decT3: 32->3, k2 s1 p2, 128->125 + recon loss -------------
// tap-paired FFMA2: (W0,W1)*(i22,i21) + (W2,W3)*(i12,i11), horizontal at end
__global__ void k_dec3(const float* __restrict__ w, const float* __restrict__ bs,
                       const float* __restrict__ x, float* __restrict__ out) {
    __shared__ float ws[384];          // w[ci][co][kh][kw] linear; pairs are u64-aligned
    __shared__ float wsum[8];
    for (int i = threadIdx.x; i < 384; i += 256) ws[i] = w[i];
    __syncthreads();
    int idx = blockIdx.x * 256 + threadIdx.x;
    float lsum = 0.f;
    if (idx < 1000000) {
        int ow = idx % 125; int t = idx / 125;
        int oh = t % 125;   int n = t / 125;
        u64 accA[3], accB[3];
        #pragma unroll
        for (int co = 0; co < 3; co++) { accA[co] = 0ull; accB[co] = 0ull; }
        const float* ib = g_d2 + n*32*16384;
        const float* p  = ib + (oh+1)*128 + (ow+1);
        const u64* wsu = (const u64*)ws;
        for (int ci = 0; ci < 32; ci++) {
            const float* q = p + ci*16384;
            u64 A = pack2(q[129], q[128]);   // (i22, i21)
            u64 B = pack2(q[1],   q[0]);     // (i12, i11)
            #pragma unroll
            for (int co = 0; co < 3; co++) {
                fma2(accA[co], wsu[ci*6 + co*2    ], A);  // (W0,W1)
                fma2(accB[co], wsu[ci*6 + co*2 + 1], B);  // (W2,W3)
            }
        }
        #pragma unroll
        for (int co = 0; co < 3; co++) {
            float2 a = unpack2(accA[co]);
            float2 c = unpack2(accB[co]);
            float v = bs[co] + a.x + a.y + c.x + c.y;
            int oi = ((n*3 + co)*125 + oh)*125 + ow;
            out[oi] = v;
            float d = v - x[oi];
            lsum += d*d;
        }
    }
    #pragma unroll
    for (int off = 16; off; off >>= 1) lsum += __shfl_down_sync(0xffffffffu, lsum, off);
    if ((threadIdx.x & 31) == 0) wsum[threadIdx.x >> 5] = lsum;
    __syncthreads();
    if (threadIdx.x == 0) {
        float s = 0.f;
        #pragma unroll
        for (int i = 0; i < 8; i++) s += wsum[i];
        atomicAdd(&g_recon, (double)s);
    }
}

// ---------------- finalize: scalars ----------------
__global__ void k_final(float* __restrict__ out) {
    double mse = g_vq_loss / (65536.0 * 64.0);
    float eq  = (float)(1.25 * mse);
    float rec = (float)g_recon;
    out[0] = eq + rec;
    out[1] = eq;
    out[2] = rec;
}

extern "C" void kernel_launch(void* const* d_in, const int* in_sizes, int n_in,
                              void* d_out, int out_size) {
    const float* x   = (const float*)d_in[0];
    const float* ew1 = (const float*)d_in[1];
    const float* eb1 = (const float*)d_in[2];
    const float* ew2 = (const float*)d_in[3];
    const float* eb2 = (const float*)d_in[4];
    const float* ew3 = (const float*)d_in[5];
    const float* eb3 = (const float*)d_in[6];
    const float* cb  = (const float*)d_in[7];
    const float* dw1 = (const float*)d_in[8];
    const float* db1 = (const float*)d_in[9];
    const float* dw2 = (const float*)d_in[10];
    const float* db2 = (const float*)d_in[11];
    const float* dw3 = (const float*)d_in[12];
    const float* db3 = (const float*)d_in[13];
    float* out = (float*)d_out;

    k_zero <<<1, 1>>>();
    k_conv1<<<(64*32*63*63 + 255)/256, 256>>>(x, ew1, eb1);
    k_conv2<<<2048, 256>>>(ew2, eb2);
    k_conv3<<<1024, 256>>>(ew3, eb3);
    k_vq   <<<256, 256>>>(cb);
    k_dec1 <<<2048, 256>>>(dw1, db1);
    k_dec2 <<<4096, 256>>>(dw2, db2);
    k_dec3 <<<3907, 256>>>(dw3, db3, x, out + 3);
    k_final<<<1, 1>>>(out);
}